// round 2
// baseline (speedup 1.0000x reference)
#include <cuda_runtime.h>

#define BB   16
#define NN   512
#define DD   16
#define KNN  20
#define CC   30
#define FF   50
#define NCLS 40
#define BQ   8          // queries per block
#define NT   512        // threads per block

// Scratch (device globals — no allocation allowed)
__device__ float g_feat[BB * NN * DD];   // stage-1 output g[b][n][d]
__device__ float g_pooled[BB * NN];      // stage-2 pooled output

__device__ __forceinline__ unsigned int forder(float f) {
    unsigned int u = __float_as_uint(f);
    return (u & 0x80000000u) ? ~u : (u | 0x80000000u);
}

// ---------------------------------------------------------------------------
// Stage 1: KNN on raw points + weighted Frechet mean (channel dim C=1).
// g[b,n,d] = sum_k softmax(w_fm1)[k] * x[b, nn_k(n), d]
// ---------------------------------------------------------------------------
__global__ __launch_bounds__(NT) void stage1_kernel(
    const float* __restrict__ x,       // [B][N][16]
    const float* __restrict__ w_fm1)   // [1][20]
{
    __shared__ float xs[DD][NN];               // transposed points, conflict-free
    __shared__ float sq[NN];
    __shared__ unsigned long long keys[NN];
    __shared__ int   sel[KNN];
    __shared__ float wc[KNN];

    const int tid = threadIdx.x;
    const int b   = blockIdx.y;

    // Load x[b] (512x16 f32 = 32KB) transposed into SMEM via float4
    const float4* x4 = (const float4*)(x + (size_t)b * NN * DD);
    #pragma unroll
    for (int i = tid; i < NN * DD / 4; i += NT) {
        int m = i >> 2, d0 = (i & 3) << 2;
        float4 v = x4[i];
        xs[d0 + 0][m] = v.x; xs[d0 + 1][m] = v.y;
        xs[d0 + 2][m] = v.z; xs[d0 + 3][m] = v.w;
    }
    if (tid == 0) {  // softmax over k of w_fm1 (20 values, trivial)
        float mx = -1e30f;
        for (int k = 0; k < KNN; k++) mx = fmaxf(mx, w_fm1[k]);
        float e[KNN], s = 0.f;
        for (int k = 0; k < KNN; k++) { e[k] = expf(w_fm1[k] - mx); s += e[k]; }
        float inv = 1.f / s;
        for (int k = 0; k < KNN; k++) wc[k] = e[k] * inv;
    }
    __syncthreads();

    {   // per-point squared norm
        float s = 0.f;
        #pragma unroll
        for (int d = 0; d < DD; d++) { float v = xs[d][tid]; s += v * v; }
        sq[tid] = s;
    }
    __syncthreads();

    for (int q = 0; q < BQ; q++) {
        const int n = blockIdx.x * BQ + q;

        // distance of point tid to query n (reference formula: sqn+sqm-2*dot)
        float dot = 0.f;
        #pragma unroll
        for (int d = 0; d < DD; d++) dot += xs[d][tid] * xs[d][n];
        float dist = sq[n] + sq[tid] - 2.f * dot;
        keys[tid] = ((unsigned long long)forder(dist) << 32) | (unsigned)tid;
        __syncthreads();

        // rank-count selection: exact top-K sorted order, ties -> lower index
        unsigned long long mk = keys[tid];
        int rank = 0;
        #pragma unroll 8
        for (int j = 0; j < NN; j++) rank += (keys[j] < mk) ? 1 : 0;
        if (rank < KNN) sel[rank] = tid;
        __syncthreads();

        if (tid < DD) {
            float acc = 0.f;
            #pragma unroll
            for (int k = 0; k < KNN; k++) acc += wc[k] * xs[tid][sel[k]];
            g_feat[((size_t)b * NN + n) * DD + tid] = acc;
        }
        __syncthreads();
    }
}

// ---------------------------------------------------------------------------
// Stage 2: KNN on g (equivalent ordering to KNN on rank-1 lifted features),
// h[d,c] = sum_k g[nn_k,d]*softmax(w_fm2)[c,k];  hm = h * w_mix1[c];
// fm2[d,f] = sum_c hm[d,c]*w_mix2[c,f];
// dist[f] = sqrt(sum_d (fm2-m_last)^2 + 1e-8);  pooled = mean_f dist.
// ---------------------------------------------------------------------------
__global__ __launch_bounds__(NT) void stage2_kernel(
    const float* __restrict__ w_fm2,   // [30][20]
    const float* __restrict__ w_mix1,  // [1][30]
    const float* __restrict__ w_mix2,  // [30][50]
    const float* __restrict__ m_last)  // [16][50]
{
    __shared__ float xs[DD][NN];
    __shared__ float sq[NN];
    __shared__ unsigned long long keys[NN];
    __shared__ int   sel[KNN];
    __shared__ float wc2[CC][KNN];
    __shared__ float wm1[CC];
    __shared__ float hm[DD][CC + 2];
    __shared__ float fm2[DD][FF + 2];
    __shared__ float distf[FF];

    const int tid = threadIdx.x;
    const int b   = blockIdx.y;

    const float4* x4 = (const float4*)(g_feat + (size_t)b * NN * DD);
    #pragma unroll
    for (int i = tid; i < NN * DD / 4; i += NT) {
        int m = i >> 2, d0 = (i & 3) << 2;
        float4 v = x4[i];
        xs[d0 + 0][m] = v.x; xs[d0 + 1][m] = v.y;
        xs[d0 + 2][m] = v.z; xs[d0 + 3][m] = v.w;
    }
    if (tid < CC) {  // per-channel softmax row of w_fm2
        const float* row = w_fm2 + tid * KNN;
        float mx = -1e30f;
        for (int k = 0; k < KNN; k++) mx = fmaxf(mx, row[k]);
        float e[KNN], s = 0.f;
        for (int k = 0; k < KNN; k++) { e[k] = expf(row[k] - mx); s += e[k]; }
        float inv = 1.f / s;
        for (int k = 0; k < KNN; k++) wc2[tid][k] = e[k] * inv;
        wm1[tid] = w_mix1[tid];
    }
    __syncthreads();

    {
        float s = 0.f;
        #pragma unroll
        for (int d = 0; d < DD; d++) { float v = xs[d][tid]; s += v * v; }
        sq[tid] = s;
    }
    __syncthreads();

    for (int q = 0; q < BQ; q++) {
        const int n = blockIdx.x * BQ + q;

        float dot = 0.f;
        #pragma unroll
        for (int d = 0; d < DD; d++) dot += xs[d][tid] * xs[d][n];
        float dist = sq[n] + sq[tid] - 2.f * dot;
        keys[tid] = ((unsigned long long)forder(dist) << 32) | (unsigned)tid;
        __syncthreads();

        unsigned long long mk = keys[tid];
        int rank = 0;
        #pragma unroll 8
        for (int j = 0; j < NN; j++) rank += (keys[j] < mk) ? 1 : 0;
        if (rank < KNN) sel[rank] = tid;
        __syncthreads();

        // hm[d][c] = w_mix1[c] * sum_k g[nn_k][d] * wc2[c][k]   (480 threads)
        if (tid < DD * CC) {
            int d = tid / CC, c = tid % CC;
            float acc = 0.f;
            #pragma unroll
            for (int k = 0; k < KNN; k++) acc += xs[d][sel[k]] * wc2[c][k];
            hm[d][c] = acc * wm1[c];
        }
        __syncthreads();

        // fm2[d][f] = sum_c hm[d][c] * w_mix2[c][f]   (800 work items)
        for (int t = tid; t < DD * FF; t += NT) {
            int d = t / FF, f = t % FF;
            float acc = 0.f;
            #pragma unroll
            for (int c = 0; c < CC; c++) acc += hm[d][c] * w_mix2[c * FF + f];
            fm2[d][f] = acc;
        }
        __syncthreads();

        if (tid < FF) {
            float s = 0.f;
            #pragma unroll
            for (int d = 0; d < DD; d++) {
                float df = fm2[d][tid] - m_last[d * FF + tid];
                s += df * df;
            }
            distf[tid] = sqrtf(s + 1e-8f);
        }
        __syncthreads();

        if (tid == 0) {
            float s = 0.f;
            for (int f = 0; f < FF; f++) s += distf[f];
            g_pooled[(size_t)b * NN + n] = s * (1.f / (float)FF);
        }
        __syncthreads();
    }
}

// ---------------------------------------------------------------------------
// Final classifier: out[b][j] = sum_n pooled[b][n]*w_cls[n][j] + b_cls[j]
// ---------------------------------------------------------------------------
__global__ __launch_bounds__(NT) void cls_kernel(
    const float* __restrict__ w_cls,   // [512][40]
    const float* __restrict__ b_cls,   // [40]
    float* __restrict__ out)           // [16][40]
{
    __shared__ float ps[NN];
    const int tid = threadIdx.x;
    const int b   = blockIdx.x;
    ps[tid] = g_pooled[(size_t)b * NN + tid];
    __syncthreads();
    if (tid < NCLS) {
        float a0 = 0.f, a1 = 0.f, a2 = 0.f, a3 = 0.f;
        #pragma unroll 4
        for (int n = 0; n < NN; n += 4) {
            a0 += ps[n + 0] * w_cls[(n + 0) * NCLS + tid];
            a1 += ps[n + 1] * w_cls[(n + 1) * NCLS + tid];
            a2 += ps[n + 2] * w_cls[(n + 2) * NCLS + tid];
            a3 += ps[n + 3] * w_cls[(n + 3) * NCLS + tid];
        }
        out[b * NCLS + tid] = (a0 + a1) + (a2 + a3) + b_cls[tid];
    }
}

extern "C" void kernel_launch(void* const* d_in, const int* in_sizes, int n_in,
                              void* d_out, int out_size)
{
    const float* x      = (const float*)d_in[0];  // inputs [16,512,16,1]
    const float* w_fm1  = (const float*)d_in[1];  // [1,20]
    const float* w_mix1 = (const float*)d_in[2];  // [1,30]
    const float* w_fm2  = (const float*)d_in[3];  // [30,20]
    const float* w_mix2 = (const float*)d_in[4];  // [30,50]
    const float* m_last = (const float*)d_in[5];  // [16,50]
    const float* w_cls  = (const float*)d_in[6];  // [512,40]
    const float* b_cls  = (const float*)d_in[7];  // [40]
    float* out = (float*)d_out;                   // [16,40]

    dim3 grid(NN / BQ, BB);
    stage1_kernel<<<grid, NT>>>(x, w_fm1);
    stage2_kernel<<<grid, NT>>>(w_fm2, w_mix1, w_mix2, m_last);
    cls_kernel<<<BB, NT>>>(w_cls, b_cls, out);
}

// round 3
// speedup vs baseline: 5.8264x; 5.8264x over previous
#include <cuda_runtime.h>

#define BB    16
#define NN    512
#define DDIM  16
#define KNN   20
#define CC    30
#define FF    50
#define NCLS  40
#define NT    256      // threads per block
#define WPB   8        // warps per block
#define QPW   8        // queries per warp
#define BPB   8        // blocks per batch (grid.x)
#define STRIDE 20      // padded floats per tile row (80B, 16B-aligned, conflict-free)
#define LLEN  17       // per-lane key list length (16 + sentinel)

// Scratch (device globals — no allocation allowed)
__device__ float g_feat[BB * NN * DDIM];
__device__ float g_pooled[BB * NN];

extern __shared__ char smem_raw[];

__device__ __forceinline__ unsigned forder(float f) {
    unsigned u = __float_as_uint(f);
    return u ^ (((unsigned)((int)u >> 31)) | 0x80000000u);
}

// ---------------------------------------------------------------------------
// Warp-cooperative exact top-K (K=20) over 512 candidates for query n.
// Returns per-lane selidx: lane r (r<20) holds the index of the r-th nearest
// neighbor (ascending distance, ties -> lowest index == stable top_k).
// ---------------------------------------------------------------------------
__device__ __forceinline__ unsigned warp_topk(
    const float* __restrict__ tile, const float* __restrict__ sq,
    unsigned long long* __restrict__ mylist, int n, int lane)
{
    // query row into registers (broadcast LDS.128)
    const float4* qr = (const float4*)(tile + n * STRIDE);
    float4 q0 = qr[0], q1 = qr[1], q2 = qr[2], q3 = qr[3];
    float sqn = sq[n];

    unsigned long long keys[16];
    #pragma unroll
    for (int i = 0; i < 16; i++) {
        int j = lane + 32 * i;
        const float4* rr = (const float4*)(tile + j * STRIDE);
        float4 r0 = rr[0], r1 = rr[1], r2 = rr[2], r3 = rr[3];
        float dot = q0.x * r0.x;
        dot = fmaf(q0.y, r0.y, dot); dot = fmaf(q0.z, r0.z, dot); dot = fmaf(q0.w, r0.w, dot);
        dot = fmaf(q1.x, r1.x, dot); dot = fmaf(q1.y, r1.y, dot); dot = fmaf(q1.z, r1.z, dot); dot = fmaf(q1.w, r1.w, dot);
        dot = fmaf(q2.x, r2.x, dot); dot = fmaf(q2.y, r2.y, dot); dot = fmaf(q2.z, r2.z, dot); dot = fmaf(q2.w, r2.w, dot);
        dot = fmaf(q3.x, r3.x, dot); dot = fmaf(q3.y, r3.y, dot); dot = fmaf(q3.z, r3.z, dot); dot = fmaf(q3.w, r3.w, dot);
        float t = sqn + sq[j];
        float dist = fmaf(-2.f, dot, t);   // == t - 2*dot, single rounding (2*dot exact)
        keys[i] = ((unsigned long long)forder(dist) << 32) | (unsigned)j;
    }

    // bitonic sort of 16 u64 keys in registers, ascending
    #pragma unroll
    for (int k = 2; k <= 16; k <<= 1) {
        #pragma unroll
        for (int j = k >> 1; j > 0; j >>= 1) {
            #pragma unroll
            for (int i = 0; i < 16; i++) {
                int l = i ^ j;
                if (l > i) {
                    bool up = ((i & k) == 0);
                    unsigned long long a = keys[i], b = keys[l];
                    bool sw = up ? (a > b) : (a < b);
                    keys[i] = sw ? b : a;
                    keys[l] = sw ? a : b;
                }
            }
        }
    }

    // spill sorted list + sentinel
    #pragma unroll
    for (int i = 0; i < 16; i++) mylist[i] = keys[i];
    mylist[16] = ~0ull;

    // 20-round warp tournament extraction
    unsigned long long head = keys[0];
    int ptr = 0;
    unsigned selidx = 0;
    #pragma unroll
    for (int r = 0; r < KNN; r++) {
        unsigned long long w = head;
        #pragma unroll
        for (int off = 16; off; off >>= 1) {
            unsigned long long o = __shfl_xor_sync(0xFFFFFFFFu, w, off);
            w = (o < w) ? o : w;
        }
        if (lane == r) selidx = (unsigned)w;          // low 32 bits = candidate index
        if (head == w) { ptr++; head = mylist[ptr]; } // unique keys -> exactly one winner
    }
    return selidx;
}

// ---------------------------------------------------------------------------
// Stage 1: KNN on raw points + weighted Frechet mean.
// g[b,n,d] = sum_k softmax(w_fm1)[k] * x[b, nn_k(n), d]
// ---------------------------------------------------------------------------
__global__ void __launch_bounds__(NT) stage1_kernel(
    const float* __restrict__ x, const float* __restrict__ w_fm1)
{
    float* tile = (float*)smem_raw;                                 // [512][20]
    float* sq   = tile + NN * STRIDE;                               // [512]
    unsigned long long* keys = (unsigned long long*)(sq + NN);      // [8][32][17]
    float* wc   = (float*)(keys + WPB * 32 * LLEN);                 // [20]

    const int tid = threadIdx.x, lane = tid & 31, warp = tid >> 5;
    const int b = blockIdx.y;

    const float4* x4 = (const float4*)(x + (size_t)b * NN * DDIM);
    #pragma unroll
    for (int i = tid; i < NN * DDIM / 4; i += NT) {
        int row = i >> 2, part = i & 3;
        *(float4*)(tile + row * STRIDE + part * 4) = x4[i];
    }
    if (tid == 0) {
        float mx = -1e30f;
        for (int k = 0; k < KNN; k++) mx = fmaxf(mx, w_fm1[k]);
        float e[KNN], s = 0.f;
        for (int k = 0; k < KNN; k++) { e[k] = expf(w_fm1[k] - mx); s += e[k]; }
        float inv = 1.f / s;
        for (int k = 0; k < KNN; k++) wc[k] = e[k] * inv;
    }
    __syncthreads();
    for (int r = tid; r < NN; r += NT) {
        float s = 0.f;
        #pragma unroll
        for (int d = 0; d < DDIM; d++) { float v = tile[r * STRIDE + d]; s = fmaf(v, v, s); }
        sq[r] = s;
    }
    __syncthreads();

    unsigned long long* mylist = keys + (warp * 32 + lane) * LLEN;
    const int qbase = blockIdx.x * (WPB * QPW) + warp * QPW;
    for (int t = 0; t < QPW; t++) {
        int n = qbase + t;
        unsigned selidx = warp_topk(tile, sq, mylist, n, lane);
        float acc = 0.f;
        #pragma unroll
        for (int k = 0; k < KNN; k++) {
            unsigned idx = __shfl_sync(0xFFFFFFFFu, selidx, k);
            float xv = tile[idx * STRIDE + (lane & 15)];
            acc = fmaf(wc[k], xv, acc);
        }
        if (lane < DDIM)
            g_feat[((size_t)b * NN + n) * DDIM + lane] = acc;
    }
}

// ---------------------------------------------------------------------------
// Stage 2: KNN on g (same ordering as KNN on rank-1 lifted features),
// fm2[d,f] = sum_k g[nn_k,d] * A[k,f], A = sum_c softmax(w_fm2)[c,:]*w_mix1[c]*w_mix2[c,:]
// pooled[n] = mean_f sqrt(sum_d (fm2[d,f]-m_last[d,f])^2 + 1e-8)
// ---------------------------------------------------------------------------
__global__ void __launch_bounds__(NT) stage2_kernel(
    const float* __restrict__ w_fm2, const float* __restrict__ w_mix1,
    const float* __restrict__ w_mix2, const float* __restrict__ m_last)
{
    float* tile = (float*)smem_raw;                                 // [512][20]
    float* sq   = tile + NN * STRIDE;                               // [512]
    unsigned long long* keys = (unsigned long long*)(sq + NN);      // [8][32][17]
    float* A    = (float*)(keys + WPB * 32 * LLEN);                 // [20][52]
    float* ms   = A + KNN * 52;                                     // [16][52]
    float* wc2  = ms + DDIM * 52;                                   // [30][20]

    const int tid = threadIdx.x, lane = tid & 31, warp = tid >> 5;
    const int b = blockIdx.y;

    const float4* x4 = (const float4*)(g_feat + (size_t)b * NN * DDIM);
    #pragma unroll
    for (int i = tid; i < NN * DDIM / 4; i += NT) {
        int row = i >> 2, part = i & 3;
        *(float4*)(tile + row * STRIDE + part * 4) = x4[i];
    }
    if (tid < CC) {
        const float* row = w_fm2 + tid * KNN;
        float mx = -1e30f;
        for (int k = 0; k < KNN; k++) mx = fmaxf(mx, row[k]);
        float e[KNN], s = 0.f;
        for (int k = 0; k < KNN; k++) { e[k] = expf(row[k] - mx); s += e[k]; }
        float inv = 1.f / s;
        for (int k = 0; k < KNN; k++) wc2[tid * KNN + k] = e[k] * inv;
    }
    for (int i = tid; i < DDIM * FF; i += NT) {
        int d = i / FF, f = i % FF;
        ms[d * 52 + f] = m_last[i];
    }
    for (int r = tid; r < NN; r += NT) {
        float s = 0.f;
        #pragma unroll
        for (int d = 0; d < DDIM; d++) { float v = tile[r * STRIDE + d]; s = fmaf(v, v, s); }
        sq[r] = s;
    }
    __syncthreads();
    // A[k][f] = sum_c wc2[c][k] * w_mix1[c] * w_mix2[c][f]
    for (int i = tid; i < KNN * FF; i += NT) {
        int k = i / FF, f = i % FF;
        float acc = 0.f;
        #pragma unroll
        for (int c = 0; c < CC; c++)
            acc = fmaf(wc2[c * KNN + k] * __ldg(w_mix1 + c), __ldg(w_mix2 + c * FF + f), acc);
        A[k * 52 + f] = acc;
    }
    __syncthreads();

    unsigned long long* mylist = keys + (warp * 32 + lane) * LLEN;
    const int qbase = blockIdx.x * (WPB * QPW) + warp * QPW;
    for (int t = 0; t < QPW; t++) {
        int n = qbase + t;
        unsigned selidx = warp_topk(tile, sq, mylist, n, lane);

        // epilogue: lane handles output channels f0=lane, f1=lane+32
        float acc0[DDIM], acc1[DDIM];
        #pragma unroll
        for (int d = 0; d < DDIM; d++) { acc0[d] = 0.f; acc1[d] = 0.f; }
        const int f0 = lane, f1 = lane + 32;
        const bool v1 = (f1 < FF);
        #pragma unroll
        for (int k = 0; k < KNN; k++) {
            unsigned idx = __shfl_sync(0xFFFFFFFFu, selidx, k);
            float a0 = A[k * 52 + f0];
            float a1 = v1 ? A[k * 52 + f1] : 0.f;
            const float* row = tile + idx * STRIDE;
            #pragma unroll
            for (int d = 0; d < DDIM; d++) {
                float xv = row[d];                 // LDS broadcast
                acc0[d] = fmaf(xv, a0, acc0[d]);
                acc1[d] = fmaf(xv, a1, acc1[d]);
            }
        }
        float s0 = 0.f, s1 = 0.f;
        #pragma unroll
        for (int d = 0; d < DDIM; d++) {
            float d0 = acc0[d] - ms[d * 52 + f0];
            s0 = fmaf(d0, d0, s0);
            float d1 = acc1[d] - (v1 ? ms[d * 52 + f1] : 0.f);
            s1 = fmaf(d1, d1, s1);
        }
        float per = sqrtf(s0 + 1e-8f) + (v1 ? sqrtf(s1 + 1e-8f) : 0.f);
        #pragma unroll
        for (int off = 16; off; off >>= 1)
            per += __shfl_xor_sync(0xFFFFFFFFu, per, off);
        if (lane == 0)
            g_pooled[(size_t)b * NN + n] = per * (1.f / (float)FF);
    }
}

// ---------------------------------------------------------------------------
// Final classifier: out[b][j] = sum_n pooled[b][n]*w_cls[n][j] + b_cls[j]
// ---------------------------------------------------------------------------
__global__ void __launch_bounds__(512) cls_kernel(
    const float* __restrict__ w_cls, const float* __restrict__ b_cls,
    float* __restrict__ out)
{
    __shared__ float ps[NN];
    const int tid = threadIdx.x;
    const int b = blockIdx.x;
    ps[tid] = g_pooled[(size_t)b * NN + tid];
    __syncthreads();
    if (tid < NCLS) {
        float a0 = 0.f, a1 = 0.f, a2 = 0.f, a3 = 0.f;
        #pragma unroll 4
        for (int n = 0; n < NN; n += 4) {
            a0 = fmaf(ps[n + 0], w_cls[(n + 0) * NCLS + tid], a0);
            a1 = fmaf(ps[n + 1], w_cls[(n + 1) * NCLS + tid], a1);
            a2 = fmaf(ps[n + 2], w_cls[(n + 2) * NCLS + tid], a2);
            a3 = fmaf(ps[n + 3], w_cls[(n + 3) * NCLS + tid], a3);
        }
        out[b * NCLS + tid] = (a0 + a1) + (a2 + a3) + b_cls[tid];
    }
}

extern "C" void kernel_launch(void* const* d_in, const int* in_sizes, int n_in,
                              void* d_out, int out_size)
{
    const float* x      = (const float*)d_in[0];  // [16,512,16,1]
    const float* w_fm1  = (const float*)d_in[1];  // [1,20]
    const float* w_mix1 = (const float*)d_in[2];  // [1,30]
    const float* w_fm2  = (const float*)d_in[3];  // [30,20]
    const float* w_mix2 = (const float*)d_in[4];  // [30,50]
    const float* m_last = (const float*)d_in[5];  // [16,50]
    const float* w_cls  = (const float*)d_in[6];  // [512,40]
    const float* b_cls  = (const float*)d_in[7];  // [40]
    float* out = (float*)d_out;                   // [16,40]

    constexpr size_t KEYB = (size_t)WPB * 32 * LLEN * 8;
    constexpr size_t S1_SMEM = (size_t)NN * STRIDE * 4 + NN * 4 + KEYB + KNN * 4;
    constexpr size_t S2_SMEM = (size_t)NN * STRIDE * 4 + NN * 4 + KEYB
                             + (KNN * 52 + DDIM * 52 + CC * KNN) * 4;

    static bool attr_done = false;
    if (!attr_done) {
        cudaFuncSetAttribute(stage1_kernel, cudaFuncAttributeMaxDynamicSharedMemorySize, (int)S1_SMEM);
        cudaFuncSetAttribute(stage2_kernel, cudaFuncAttributeMaxDynamicSharedMemorySize, (int)S2_SMEM);
        attr_done = true;
    }

    dim3 grid(BPB, BB);
    stage1_kernel<<<grid, NT, S1_SMEM>>>(x, w_fm1);
    stage2_kernel<<<grid, NT, S2_SMEM>>>(w_fm2, w_mix1, w_mix2, m_last);
    cls_kernel<<<BB, 512>>>(w_cls, b_cls, out);
}

// round 4
// speedup vs baseline: 9.8708x; 1.6942x over previous
#include <cuda_runtime.h>

#define BB    16
#define NN    512
#define DDIM  16
#define KNN   20
#define CC    30
#define FF    50
#define NCLS  40
#define NT    256      // threads per block
#define WPB   8        // warps per block
#define QPW   4        // queries per warp
#define BPB   16       // blocks per batch (grid.x)
#define STRIDE 20      // padded floats per tile row (80B, 16B-aligned)
#define NSLOT 17       // per-lane sorted list length (16 + sentinel)
#define LSTRIDE (WPB * 32)   // list slot stride in u64 (lane-major, conflict-free)

// Scratch (device globals — no allocation allowed)
__device__ float g_feat[BB * NN * DDIM];
__device__ float g_pooled[BB * NN];

extern __shared__ char smem_raw[];

__device__ __forceinline__ unsigned forder(float f) {
    unsigned u = __float_as_uint(f);
    return u ^ (((unsigned)((int)u >> 31)) | 0x80000000u);
}

// ---------------------------------------------------------------------------
// Warp-cooperative exact top-K (K=20) over 512 candidates for query n.
// Lane r (r<20) ends holding selidx = index of the r-th nearest neighbor
// (ascending distance, ties -> lowest index == stable jax top_k semantics).
// mylane_list points at this lane's slot-0 entry; slots are LSTRIDE apart.
// ---------------------------------------------------------------------------
__device__ __forceinline__ unsigned warp_topk(
    const float* __restrict__ tile, const float* __restrict__ sq,
    unsigned long long* __restrict__ mylane_list, int n, int lane)
{
    const float4* qr = (const float4*)(tile + n * STRIDE);
    float4 q0 = qr[0], q1 = qr[1], q2 = qr[2], q3 = qr[3];
    float sqn = sq[n];

    unsigned long long keys[16];
    #pragma unroll
    for (int i = 0; i < 16; i++) {
        int j = lane + 32 * i;
        const float4* rr = (const float4*)(tile + j * STRIDE);
        float4 r0 = rr[0], r1 = rr[1], r2 = rr[2], r3 = rr[3];
        float dot = q0.x * r0.x;
        dot = fmaf(q0.y, r0.y, dot); dot = fmaf(q0.z, r0.z, dot); dot = fmaf(q0.w, r0.w, dot);
        dot = fmaf(q1.x, r1.x, dot); dot = fmaf(q1.y, r1.y, dot); dot = fmaf(q1.z, r1.z, dot); dot = fmaf(q1.w, r1.w, dot);
        dot = fmaf(q2.x, r2.x, dot); dot = fmaf(q2.y, r2.y, dot); dot = fmaf(q2.z, r2.z, dot); dot = fmaf(q2.w, r2.w, dot);
        dot = fmaf(q3.x, r3.x, dot); dot = fmaf(q3.y, r3.y, dot); dot = fmaf(q3.z, r3.z, dot); dot = fmaf(q3.w, r3.w, dot);
        float t = sqn + sq[j];
        float dist = fmaf(-2.f, dot, t);
        keys[i] = ((unsigned long long)forder(dist) << 32) | (unsigned)j;
    }

    // in-register bitonic sort of 16 u64 keys, ascending
    #pragma unroll
    for (int k = 2; k <= 16; k <<= 1) {
        #pragma unroll
        for (int j = k >> 1; j > 0; j >>= 1) {
            #pragma unroll
            for (int i = 0; i < 16; i++) {
                int l = i ^ j;
                if (l > i) {
                    bool up = ((i & k) == 0);
                    unsigned long long a = keys[i], b = keys[l];
                    bool sw = up ? (a > b) : (a < b);
                    keys[i] = sw ? b : a;
                    keys[l] = sw ? a : b;
                }
            }
        }
    }

    // spill sorted list + sentinel (lane-major slots: conflict-free)
    #pragma unroll
    for (int i = 0; i < 16; i++) mylane_list[i * LSTRIDE] = keys[i];
    mylane_list[16 * LSTRIDE] = ~0ull;

    // 20 extraction rounds via 2x REDUX.MIN.U32 (hi = dist bits, lo = idx)
    unsigned hi = (unsigned)(keys[0] >> 32);
    unsigned lo = (unsigned)keys[0];
    int ptr = 0;
    unsigned selidx = 0;
    #pragma unroll
    for (int r = 0; r < KNN; r++) {
        unsigned mhi = __reduce_min_sync(0xFFFFFFFFu, hi);
        unsigned cl  = (hi == mhi) ? lo : 0xFFFFFFFFu;
        unsigned mlo = __reduce_min_sync(0xFFFFFFFFu, cl);
        if (lane == r) selidx = mlo;                 // winner's low 32 = index
        if (hi == mhi && lo == mlo) {                // unique keys -> one winner
            ptr++;
            unsigned long long h = mylane_list[ptr * LSTRIDE];
            hi = (unsigned)(h >> 32); lo = (unsigned)h;
        }
    }
    return selidx;
}

// ---------------------------------------------------------------------------
// Stage 1: KNN on raw points + weighted Frechet mean.
// ---------------------------------------------------------------------------
__global__ void __launch_bounds__(NT, 2) stage1_kernel(
    const float* __restrict__ x, const float* __restrict__ w_fm1)
{
    float* tile = (float*)smem_raw;                                 // [512][20]
    float* sq   = tile + NN * STRIDE;                               // [512]
    unsigned long long* lists = (unsigned long long*)(sq + NN);     // [17][256]
    float* wc   = (float*)(lists + NSLOT * LSTRIDE);                // [20]

    const int tid = threadIdx.x, lane = tid & 31, warp = tid >> 5;
    const int b = blockIdx.y;

    const float4* x4 = (const float4*)(x + (size_t)b * NN * DDIM);
    #pragma unroll
    for (int i = tid; i < NN * DDIM / 4; i += NT) {
        int row = i >> 2, part = i & 3;
        *(float4*)(tile + row * STRIDE + part * 4) = x4[i];
    }
    if (tid == 0) {
        float mx = -1e30f;
        for (int k = 0; k < KNN; k++) mx = fmaxf(mx, w_fm1[k]);
        float e[KNN], s = 0.f;
        for (int k = 0; k < KNN; k++) { e[k] = expf(w_fm1[k] - mx); s += e[k]; }
        float inv = 1.f / s;
        for (int k = 0; k < KNN; k++) wc[k] = e[k] * inv;
    }
    __syncthreads();
    for (int r = tid; r < NN; r += NT) {
        float s = 0.f;
        #pragma unroll
        for (int d = 0; d < DDIM; d++) { float v = tile[r * STRIDE + d]; s = fmaf(v, v, s); }
        sq[r] = s;
    }
    __syncthreads();

    unsigned long long* mylane_list = lists + warp * 32 + lane;
    const int qbase = blockIdx.x * (WPB * QPW) + warp * QPW;
    #pragma unroll 1
    for (int t = 0; t < QPW; t++) {
        int n = qbase + t;
        unsigned selidx = warp_topk(tile, sq, mylane_list, n, lane);
        float acc = 0.f;
        #pragma unroll
        for (int k = 0; k < KNN; k++) {
            unsigned idx = __shfl_sync(0xFFFFFFFFu, selidx, k);
            float xv = tile[idx * STRIDE + (lane & 15)];
            acc = fmaf(wc[k], xv, acc);
        }
        if (lane < DDIM)
            g_feat[((size_t)b * NN + n) * DDIM + lane] = acc;
    }
}

// ---------------------------------------------------------------------------
// Stage 2: KNN on g (same ordering as KNN on the rank-1 lifted features),
// fm2[d,f] = sum_k g[nn_k,d]*A[k,f],  A = sum_c softmax(w_fm2)[c,:]*w_mix1[c]*w_mix2[c,:]
// pooled[n] = mean_f sqrt(sum_d (fm2[d,f]-m_last[d,f])^2 + 1e-8)
// ---------------------------------------------------------------------------
__global__ void __launch_bounds__(NT, 2) stage2_kernel(
    const float* __restrict__ w_fm2, const float* __restrict__ w_mix1,
    const float* __restrict__ w_mix2, const float* __restrict__ m_last)
{
    float* tile = (float*)smem_raw;                                 // [512][20]
    float* sq   = tile + NN * STRIDE;                               // [512]
    unsigned long long* lists = (unsigned long long*)(sq + NN);     // [17][256]
    float* A    = (float*)(lists + NSLOT * LSTRIDE);                // [20][52]
    float* ms   = A + KNN * 52;                                     // [16][52]
    float* wc2  = ms + DDIM * 52;                                   // [30][20]

    const int tid = threadIdx.x, lane = tid & 31, warp = tid >> 5;
    const int b = blockIdx.y;

    const float4* x4 = (const float4*)(g_feat + (size_t)b * NN * DDIM);
    #pragma unroll
    for (int i = tid; i < NN * DDIM / 4; i += NT) {
        int row = i >> 2, part = i & 3;
        *(float4*)(tile + row * STRIDE + part * 4) = x4[i];
    }
    if (tid < CC) {
        const float* row = w_fm2 + tid * KNN;
        float mx = -1e30f;
        for (int k = 0; k < KNN; k++) mx = fmaxf(mx, row[k]);
        float e[KNN], s = 0.f;
        for (int k = 0; k < KNN; k++) { e[k] = expf(row[k] - mx); s += e[k]; }
        float inv = 1.f / s;
        for (int k = 0; k < KNN; k++) wc2[tid * KNN + k] = e[k] * inv;
    }
    for (int i = tid; i < DDIM * FF; i += NT) {
        int d = i / FF, f = i % FF;
        ms[d * 52 + f] = m_last[i];
    }
    for (int r = tid; r < NN; r += NT) {
        float s = 0.f;
        #pragma unroll
        for (int d = 0; d < DDIM; d++) { float v = tile[r * STRIDE + d]; s = fmaf(v, v, s); }
        sq[r] = s;
    }
    __syncthreads();
    for (int i = tid; i < KNN * FF; i += NT) {
        int k = i / FF, f = i % FF;
        float acc = 0.f;
        #pragma unroll
        for (int c = 0; c < CC; c++)
            acc = fmaf(wc2[c * KNN + k] * __ldg(w_mix1 + c), __ldg(w_mix2 + c * FF + f), acc);
        A[k * 52 + f] = acc;
    }
    __syncthreads();

    unsigned long long* mylane_list = lists + warp * 32 + lane;
    const int qbase = blockIdx.x * (WPB * QPW) + warp * QPW;
    #pragma unroll 1
    for (int t = 0; t < QPW; t++) {
        int n = qbase + t;
        unsigned selidx = warp_topk(tile, sq, mylane_list, n, lane);

        float acc0[DDIM], acc1[DDIM];
        #pragma unroll
        for (int d = 0; d < DDIM; d++) { acc0[d] = 0.f; acc1[d] = 0.f; }
        const int f0 = lane, f1 = lane + 32;
        const bool v1 = (f1 < FF);
        #pragma unroll
        for (int k = 0; k < KNN; k++) {
            unsigned idx = __shfl_sync(0xFFFFFFFFu, selidx, k);
            float a0 = A[k * 52 + f0];
            float a1 = v1 ? A[k * 52 + f1] : 0.f;
            const float* row = tile + idx * STRIDE;
            #pragma unroll
            for (int d = 0; d < DDIM; d++) {
                float xv = row[d];                   // LDS broadcast
                acc0[d] = fmaf(xv, a0, acc0[d]);
                acc1[d] = fmaf(xv, a1, acc1[d]);
            }
        }
        float s0 = 0.f, s1 = 0.f;
        #pragma unroll
        for (int d = 0; d < DDIM; d++) {
            float d0 = acc0[d] - ms[d * 52 + f0];
            s0 = fmaf(d0, d0, s0);
            float d1 = acc1[d] - (v1 ? ms[d * 52 + f1] : 0.f);
            s1 = fmaf(d1, d1, s1);
        }
        float per = sqrtf(s0 + 1e-8f) + (v1 ? sqrtf(s1 + 1e-8f) : 0.f);
        #pragma unroll
        for (int off = 16; off; off >>= 1)
            per += __shfl_xor_sync(0xFFFFFFFFu, per, off);
        if (lane == 0)
            g_pooled[(size_t)b * NN + n] = per * (1.f / (float)FF);
    }
}

// ---------------------------------------------------------------------------
// Final classifier: out[b][j] = sum_n pooled[b][n]*w_cls[n][j] + b_cls[j]
// ---------------------------------------------------------------------------
__global__ void __launch_bounds__(512) cls_kernel(
    const float* __restrict__ w_cls, const float* __restrict__ b_cls,
    float* __restrict__ out)
{
    __shared__ float ps[NN];
    const int tid = threadIdx.x;
    const int b = blockIdx.x;
    ps[tid] = g_pooled[(size_t)b * NN + tid];
    __syncthreads();
    if (tid < NCLS) {
        float a0 = 0.f, a1 = 0.f, a2 = 0.f, a3 = 0.f;
        #pragma unroll 4
        for (int n = 0; n < NN; n += 4) {
            a0 = fmaf(ps[n + 0], w_cls[(n + 0) * NCLS + tid], a0);
            a1 = fmaf(ps[n + 1], w_cls[(n + 1) * NCLS + tid], a1);
            a2 = fmaf(ps[n + 2], w_cls[(n + 2) * NCLS + tid], a2);
            a3 = fmaf(ps[n + 3], w_cls[(n + 3) * NCLS + tid], a3);
        }
        out[b * NCLS + tid] = (a0 + a1) + (a2 + a3) + b_cls[tid];
    }
}

extern "C" void kernel_launch(void* const* d_in, const int* in_sizes, int n_in,
                              void* d_out, int out_size)
{
    const float* x      = (const float*)d_in[0];  // [16,512,16,1]
    const float* w_fm1  = (const float*)d_in[1];  // [1,20]
    const float* w_mix1 = (const float*)d_in[2];  // [1,30]
    const float* w_fm2  = (const float*)d_in[3];  // [30,20]
    const float* w_mix2 = (const float*)d_in[4];  // [30,50]
    const float* m_last = (const float*)d_in[5];  // [16,50]
    const float* w_cls  = (const float*)d_in[6];  // [512,40]
    const float* b_cls  = (const float*)d_in[7];  // [40]
    float* out = (float*)d_out;                   // [16,40]

    constexpr size_t LISTB   = (size_t)NSLOT * LSTRIDE * 8;
    constexpr size_t S1_SMEM = (size_t)NN * STRIDE * 4 + NN * 4 + LISTB + KNN * 4;
    constexpr size_t S2_SMEM = (size_t)NN * STRIDE * 4 + NN * 4 + LISTB
                             + (KNN * 52 + DDIM * 52 + CC * KNN) * 4;

    cudaFuncSetAttribute(stage1_kernel, cudaFuncAttributeMaxDynamicSharedMemorySize, (int)S1_SMEM);
    cudaFuncSetAttribute(stage2_kernel, cudaFuncAttributeMaxDynamicSharedMemorySize, (int)S2_SMEM);

    dim3 grid(BPB, BB);
    stage1_kernel<<<grid, NT, S1_SMEM>>>(x, w_fm1);
    stage2_kernel<<<grid, NT, S2_SMEM>>>(w_fm2, w_mix1, w_mix2, m_last);
    cls_kernel<<<BB, 512>>>(w_cls, b_cls, out);
}